// round 8
// baseline (speedup 1.0000x reference)
#include <cuda_runtime.h>

// ActiveParticles step, N=4096 — spatially binned (64x64 grid, counting sort).
// Inputs: positions[N,2] f32, orientations[N,2] f32, Deltas[1] f32,
//         rot_noise[N] f32, trans_noise[N,2] f32.
// Output: [5, N, 2] f32 = {new_p, new_u, orientation_sums, leftturns, rightturns}.

#define NMAX  4096
#define GDIM  64
#define CELLS (GDIM * GDIM)

// Grid geometry: span [-2.24e-3, 2.24e-3], cell 7e-5 >= ROC (2.815e-5).
// Clamped cell mapping is monotone & non-expanding: any pair within ROC is in
// adjacent cells, outliers included. Collision moves (~1e-5) << cell, so the
// one-time binning stays valid for all 3 collision sweeps (radius 6.3e-6).
#define XMIN  (-2.24e-3f)
#define INVCS (14285.714285714286f)   // 1 / 7e-5

static __device__ float2   g_cms;
static __device__ float2   g_part[32];        // per-block partial sums for mean
static __device__ float4   g_pu[NMAX];        // orig order (p.x,p.y,u.x,u.y)
static __device__ int      g_ci[NMAX];        // cell id per orig particle
static __device__ unsigned g_cnt[CELLS];
static __device__ unsigned g_start[CELLS + 1];
static __device__ unsigned g_cur[CELLS];
static __device__ float4   g_spu[NMAX];       // sorted (p,u)
static __device__ int      g_sorig[NMAX];     // sorted -> orig index
static __device__ int      g_scell[NMAX];     // sorted -> cell id
static __device__ float2   g_sposA[NMAX];     // sorted positions ping
static __device__ float2   g_sposB[NMAX];     // sorted positions pong

__device__ __forceinline__ float wsum(float v) {
#pragma unroll
    for (int o = 16; o; o >>= 1) v += __shfl_xor_sync(0xffffffffu, v, o);
    return v;
}

__device__ __forceinline__ unsigned uwscan(unsigned v, int lane) {  // inclusive
#pragma unroll
    for (int o = 1; o < 32; o <<= 1) {
        unsigned t = __shfl_up_sync(0xffffffffu, v, o);
        if (lane >= o) v += t;
    }
    return v;
}

__device__ __forceinline__ float anglewrap(float diff) {
    const float PI_F = 3.1415927410125732f;
    if (diff <= -PI_F) diff = diff - PI_F * floorf(diff / PI_F);  // jnp.mod(diff, PI)
    if (diff >= PI_F) diff -= 2.0f * PI_F;
    return diff;
}

__device__ __forceinline__ float anglediff(float ax, float ay, float bx, float by) {
    return anglewrap(atan2f(ay, ax) - atan2f(by, bx));
}

__device__ __forceinline__ int cell_of(float x, float y) {
    int cx = __float2int_rd((x - XMIN) * INVCS);
    int cy = __float2int_rd((y - XMIN) * INVCS);
    cx = max(0, min(GDIM - 1, cx));
    cy = max(0, min(GDIM - 1, cy));
    return cy * GDIM + cx;
}

// ---- A: zero counts --------------------------------------------------------------
__global__ void zero_kernel() {
    int t = blockIdx.x * blockDim.x + threadIdx.x;
    if (t < CELLS) g_cnt[t] = 0u;
}

// ---- B: pack, bin (count), per-block position partials ---------------------------
__global__ void bin_kernel(const float2* __restrict__ p, const float2* __restrict__ u, int n) {
    __shared__ float2 sh[8];
    int i = blockIdx.x * blockDim.x + threadIdx.x;
    float2 pp = make_float2(0.f, 0.f);
    if (i < n) {
        pp = p[i];
        float2 uu = u[i];
        g_pu[i] = make_float4(pp.x, pp.y, uu.x, uu.y);
        int c = cell_of(pp.x, pp.y);
        g_ci[i] = c;
        atomicAdd(&g_cnt[c], 1u);
    }
    float sx = wsum(pp.x), sy = wsum(pp.y);
    int lane = threadIdx.x & 31, w = threadIdx.x >> 5;
    if (lane == 0) sh[w] = make_float2(sx, sy);
    __syncthreads();
    if (threadIdx.x == 0) {
        float ax = 0.f, ay = 0.f;
        for (int k = 0; k < (int)(blockDim.x >> 5); k++) { ax += sh[k].x; ay += sh[k].y; }
        g_part[blockIdx.x] = make_float2(ax, ay);
    }
}

// ---- C: exclusive scan of 4096 counts (1 block, 1024 thr) + finish mean ----------
__global__ void scan_kernel(int n, int nbin) {
    __shared__ unsigned wtot[32];
    int t = threadIdx.x, lane = t & 31, w = t >> 5;
    unsigned c0 = g_cnt[4 * t], c1 = g_cnt[4 * t + 1];
    unsigned c2 = g_cnt[4 * t + 2], c3 = g_cnt[4 * t + 3];
    unsigned s = c0 + c1 + c2 + c3;
    unsigned inc = uwscan(s, lane);
    if (lane == 31) wtot[w] = inc;
    __syncthreads();
    if (w == 0) wtot[lane] = uwscan(wtot[lane], lane);
    __syncthreads();
    unsigned base = (w ? wtot[w - 1] : 0u) + inc - s;   // exclusive prefix for thread
    g_start[4 * t] = base;
    g_start[4 * t + 1] = base + c0;
    g_start[4 * t + 2] = base + c0 + c1;
    g_start[4 * t + 3] = base + c0 + c1 + c2;
    g_cur[4 * t] = base;
    g_cur[4 * t + 1] = base + c0;
    g_cur[4 * t + 2] = base + c0 + c1;
    g_cur[4 * t + 3] = base + c0 + c1 + c2;
    if (t == 1023) g_start[CELLS] = base + s;
    // mean(p): reduce g_part
    if (w == 0) {
        float2 v = (lane < nbin) ? g_part[lane] : make_float2(0.f, 0.f);
        float ax = wsum(v.x), ay = wsum(v.y);
        if (lane == 0) {
            float invn = 1.0f / fmaxf((float)n, 1.0f);   // max(n_a,1), n_a=n (mask_ra all-true)
            g_cms = make_float2(ax * invn, ay * invn);
        }
    }
}

// ---- D: scatter into sorted arrays ----------------------------------------------
__global__ void scatter_kernel(int n) {
    int i = blockIdx.x * blockDim.x + threadIdx.x;
    if (i >= n) return;
    int c = g_ci[i];
    unsigned slot = atomicAdd(&g_cur[c], 1u);
    g_spu[slot] = g_pu[i];
    g_sorig[slot] = i;
    g_scell[slot] = c;
}

// ---- E: per-cell insertion sort by orig index -> deterministic layout ------------
__global__ void cellsort_kernel() {
    int c = blockIdx.x * blockDim.x + threadIdx.x;
    if (c >= CELLS) return;
    int a = (int)g_start[c], b = (int)g_start[c + 1];
    for (int i = a + 1; i < b; i++) {
        float4 key = g_spu[i];
        int ko = g_sorig[i];
        int j = i - 1;
        while (j >= a && g_sorig[j] > ko) {
            g_spu[j + 1] = g_spu[j];
            g_sorig[j + 1] = g_sorig[j];
            j--;
        }
        g_spu[j + 1] = key;
        g_sorig[j + 1] = ko;
    }
}

// ---- F: main pass — warp per sorted slot, 3x3 cell neighborhood ------------------
__global__ void __launch_bounds__(128) main_kernel(
        const float* __restrict__ deltas, const float* __restrict__ rnoise,
        const float2* __restrict__ tn, float* __restrict__ out, int n) {
    const int lane = threadIdx.x & 31;
    const int s = blockIdx.x * 4 + (threadIdx.x >> 5);
    if (s >= n) return;

    const float4 me = g_spu[s];
    const float pix = me.x, piy = me.y, uix = me.z, uiy = me.w;
    const int c = g_scell[s];
    const int cx = c & (GDIM - 1), cy = c >> 6;

    const float RR2  = (float)(8e-6 * 8e-6);
    const float ROCf = (float)(2.5e-5 + 3.15e-6);
    const float ROC2 = ROCf * ROCf;
    const unsigned uRR2 = __float_as_uint(RR2);

    float nr = 0.f, srx = 0.f, sry = 0.f, osx = 0.f, osy = 0.f;

    const int cx0 = max(cx - 1, 0), cx1 = min(cx + 1, GDIM - 1);
#pragma unroll
    for (int dy = -1; dy <= 1; dy++) {
        int ry = cy + dy;
        if ((unsigned)ry < (unsigned)GDIM) {
            int a = (int)g_start[ry * GDIM + cx0];
            int b = (int)g_start[ry * GDIM + cx1 + 1];
            for (int idx = a + lane; idx < b; idx += 32) {
                float4 aj = g_spu[idx];
                float dx = aj.x - pix, dyv = aj.y - piy;
                float d2 = fmaf(dx, dx, dyv * dyv);
                if (d2 <= ROC2) {                        // mask_ro (includes self)
                    osx += aj.z; osy += aj.w;
                    // inside_Rr excl. self: 0 < d2 <= RR2
                    if ((__float_as_uint(d2) - 1u) < uRR2) {
                        // in_front: wrap(angle(dir)-angle(u_j)) < pi/2
                        //   <=> !(dot<=0 && cross>=0)
                        float cc = dx * aj.z + dyv * aj.w;
                        float ss = aj.z * dyv - aj.w * dx;
                        if (!(cc <= 0.0f && ss >= 0.0f)) { nr += 1.f; srx += aj.x; sry += aj.y; }
                    }
                }
            }
        }
    }
    nr = wsum(nr); srx = wsum(srx); sry = wsum(sry); osx = wsum(osx); osy = wsum(osy);

    // ---- per-particle epilogue (all lanes redundant, lane 0 writes) ----
    float sgn = (nr > 0.f) ? 1.0f : 0.0f;
    float invr = 1.0f / fmaxf(nr, 1.0f);
    float dax = -(srx * invr - pix * sgn);
    float day = -(sry * invr - piy * sgn);

    float2 cms = g_cms;
    float Psx = cms.x - pix;                             // sign(n_a) == 1
    float Psy = cms.y - piy;

    float Delta = __ldg(&deltas[0]);
    float cd = cosf(Delta), sd = sinf(Delta);
    float lx = Psx * cd - Psy * sd, ly = Psx * sd + Psy * cd;   // Ps*e^{+iD}
    float rx = Psx * cd + Psy * sd, ry = Psy * cd - Psx * sd;   // Ps*e^{-iD}

    const float EPSF = 1e-14f;
    float nbn = fmaxf(sqrtf(osx * osx + osy * osy + 1e-30f), EPSF);
    float naL = fmaxf(sqrtf(lx * lx + ly * ly + 1e-30f), EPSF);
    float naR = fmaxf(sqrtf(rx * rx + ry * ry + 1e-30f), EPSF);
    float csL = (lx * osx + ly * osy) / (naL * nbn);
    float csR = (rx * osx + ry * osy) / (naR * nbn);
    bool left_closer = (csL >= csR);
    float bx = left_closer ? lx : rx;
    float by = left_closer ? ly : ry;

    float d_abs = sqrtf(dax * dax + day * day);
    float ang;
    if (d_abs > 0.f) {
        ang = anglediff(dax, day, uix, uiy);
    } else {
        float babs = sqrtf(bx * bx + by * by);
        float bsx = (babs > 0.f) ? bx : 1.0f;
        float bsy = (babs > 0.f) ? by : 0.0f;
        ang = anglediff(bsx, bsy, uix, uiy);
    }

    const int io = g_sorig[s];
    const float C1   = (float)(0.2 * 25.0 * 0.0028);     // dt*Gamma*DR
    const float S2DR = (float)0.07483314773547883;       // sqrt(2*DR)
    const float SDT  = (float)0.4472135954999579;        // sqrt(dt)
    float phi = C1 * sinf(ang) + rnoise[io] * S2DR * SDT;
    float cr = cosf(phi), sr = sinf(phi);
    float nux = uix * cr - uiy * sr;
    float nuy = uix * sr + uiy * cr;

    const float DTV = (float)(0.2 * 5e-7);
    const float CSH = (float)0.7071067811865476;         // sqrt(0.5)
    const float C2T = (float)1.6733200530681511e-07;     // sqrt(2*DT_trans)
    float2 t = __ldg(&tn[io]);
    float tx = DTV * uix + ((t.x * CSH) * C2T) * SDT;
    float ty = DTV * uiy + ((t.y * CSH) * C2T) * SDT;

    if (lane == 0) {
        g_sposA[s] = make_float2(pix + tx, piy + ty);
        int b = 2 * n;
        out[1 * b + 2 * io + 0] = nux;  out[1 * b + 2 * io + 1] = nuy;
        out[2 * b + 2 * io + 0] = osx;  out[2 * b + 2 * io + 1] = osy;
        out[3 * b + 2 * io + 0] = lx;   out[3 * b + 2 * io + 1] = ly;
        out[4 * b + 2 * io + 0] = rx;   out[4 * b + 2 * io + 1] = ry;
    }
}

// ---- G: collision sweep — warp per sorted slot, 3x3 cells ------------------------
// pass 0: A->B, 1: B->A, 2: A->out (scattered to orig order).
__global__ void __launch_bounds__(128) collide_kernel(int pass, float* __restrict__ out, int n) {
    const float2* __restrict__ src = (pass == 1) ? g_sposB : g_sposA;
    const int lane = threadIdx.x & 31;
    const int s = blockIdx.x * 4 + (threadIdx.x >> 5);
    if (s >= n) return;

    const float2 pi = src[s];
    const int c = g_scell[s];
    const int cx = c & (GDIM - 1), cy = c >> 6;

    const float TH2 = (float)(2.0 * 3.15e-6) * (float)(2.0 * 3.15e-6);
    const float C21 = (float)(2.1 * 3.15e-6);
    const unsigned uTH2 = __float_as_uint(TH2);

    float mvx = 0.f, mvy = 0.f;
    const int cx0 = max(cx - 1, 0), cx1 = min(cx + 1, GDIM - 1);
#pragma unroll
    for (int dy = -1; dy <= 1; dy++) {
        int ry = cy + dy;
        if ((unsigned)ry < (unsigned)GDIM) {
            int a = (int)g_start[ry * GDIM + cx0];
            int b = (int)g_start[ry * GDIM + cx1 + 1];
            for (int idx = a + lane; idx < b; idx += 32) {
                float2 pj = src[idx];
                float dx = pj.x - pi.x, dyv = pj.y - pi.y;
                float d2 = fmaf(dx, dx, dyv * dyv);
                // hit iff 0 < d2 <= TH2 (d2==0 <=> self)
                if ((__float_as_uint(d2) - 1u) < uTH2) {
                    float ab = sqrtf(d2);
                    float sc = (C21 - ab) * 0.5f / ab;
                    mvx += dx * sc; mvy += dyv * sc;
                }
            }
        }
    }
    mvx = wsum(mvx); mvy = wsum(mvy);
    if (lane == 0) {
        float2 np = make_float2(pi.x - mvx, pi.y - mvy);
        if (pass == 0) g_sposB[s] = np;
        else if (pass == 1) g_sposA[s] = np;
        else {
            int io = g_sorig[s];
            out[2 * io + 0] = np.x;
            out[2 * io + 1] = np.y;
        }
    }
}

extern "C" void kernel_launch(void* const* d_in, const int* in_sizes, int n_in,
                              void* d_out, int out_size) {
    const float* pos = (const float*)d_in[0];
    const float* ori = (const float*)d_in[1];
    const float* del = (const float*)d_in[2];
    const float* rno = (const float*)d_in[3];
    const float* tno = (const float*)d_in[4];
    float* out = (float*)d_out;
    const int n = in_sizes[3];                   // rot_noise has N elements
    const int nbin = (n + 255) / 256;            // bin_kernel blocks (<=32)

    zero_kernel<<<(CELLS + 1023) / 1024, 1024>>>();
    bin_kernel<<<nbin, 256>>>((const float2*)pos, (const float2*)ori, n);
    scan_kernel<<<1, 1024>>>(n, nbin);
    scatter_kernel<<<(n + 255) / 256, 256>>>(n);
    cellsort_kernel<<<(CELLS + 255) / 256, 256>>>();
    main_kernel<<<(n + 3) / 4, 128>>>(del, rno, (const float2*)tno, out, n);
    collide_kernel<<<(n + 3) / 4, 128>>>(0, nullptr, n);
    collide_kernel<<<(n + 3) / 4, 128>>>(1, nullptr, n);
    collide_kernel<<<(n + 3) / 4, 128>>>(2, out, n);
}